// round 6
// baseline (speedup 1.0000x reference)
#include <cuda_runtime.h>

// Problem constants
#define NSTEPS   8192
#define NPTS     8193            // positions per chain (incl. leading zero row)
#define NCHAIN   2
#define CONFLEN  16388

// Chunking
#define CHUNK    128
#define NCHUNK   68                              // PADN / CHUNK
#define PADN     (NCHUNK * CHUNK)                // 8704
#define NPAIR    (NCHUNK * (NCHUNK + 1) / 2)     // 2346 chunk pairs (cj >= ci)
#define NBLOCKS  (NPAIR * NCHAIN)                // 4692

#define PBLOCK   512                             // 4 j-segments x 128 i
#define JSEG     32                              // j's per thread

// Scaled-space cutoff: dropped pair value <= 2^(-0.5*64) = 2.3e-10
#define DCUT_HAT 8.0f

// Fixed-point scale for deterministic integer accumulation
#define FXSCALE  16777216.0f     // 2^24

// Scratch (no allocations allowed; zero-initialized)
__device__ float4 g_pts[NCHAIN][PADN];           // (x_hat, y_hat, z_hat, a)
__device__ float4 g_cb[NCHAIN * NCHUNK];         // chunk bounds: (cx,cy,cz,r)
__device__ unsigned long long g_acc;             // fixed-point sum
__device__ unsigned int g_count;                 // finished-block counter

// ---------------------------------------------------------------------------
// Setup: positions (prefix sum of unit steps), pre-scale, pads, chunk bounds.
// One block (1024 threads) per chain; each thread handles 8 consecutive steps.
// ---------------------------------------------------------------------------
__global__ void setup_kernel(const float* __restrict__ conf) {
    const int chain = blockIdx.x;
    const float* cf = conf + chain * CONFLEN;
    const int t = threadIdx.x;                 // 0..1023
    const int lane = t & 31, warp = t >> 5;

    const float TWO_PI = 6.2831853071795864769f;

    // local steps + inclusive local prefix
    float px[8], py[8], pz[8];
    float sx = 0.f, sy = 0.f, sz = 0.f;
    const float2* cp = (const float2*)(cf + 4);  // (r1, r2) pairs
    #pragma unroll
    for (int m = 0; m < 8; m++) {
        int k = t * 8 + m;
        float2 rr = cp[k];
        float r1 = rr.x + 0.5f;
        float r2 = rr.y + 0.5f;
        float z  = 1.0f - 2.0f * r2;                    // cos(theta)
        float sth = sqrtf(fmaxf(1.0f - z * z, 0.0f));   // sin(theta)
        float s, c;
        __sincosf(r1 * TWO_PI, &s, &c);
        sx += sth * c;
        sy += sth * s;
        sz += z;
        px[m] = sx; py[m] = sy; pz[m] = sz;
    }

    // warp inclusive scan of thread totals
    float tx = sx, ty = sy, tz = sz;
    #pragma unroll
    for (int d = 1; d < 32; d <<= 1) {
        float ox = __shfl_up_sync(0xffffffffu, tx, d);
        float oy = __shfl_up_sync(0xffffffffu, ty, d);
        float oz = __shfl_up_sync(0xffffffffu, tz, d);
        if (lane >= d) { tx += ox; ty += oy; tz += oz; }
    }

    __shared__ float3 wtot[32];
    __shared__ float3 woff[32];
    __shared__ float4 lastpt;
    if (lane == 31) wtot[warp] = make_float3(tx, ty, tz);
    __syncthreads();
    if (t == 0) {
        float ax = 0.f, ay = 0.f, az = 0.f;
        #pragma unroll
        for (int w = 0; w < 32; w++) {
            float3 v = wtot[w];
            woff[w] = make_float3(ax, ay, az);
            ax += v.x; ay += v.y; az += v.z;
        }
    }
    __syncthreads();

    // exclusive base for this thread
    float bx = woff[warp].x + (tx - sx);
    float by = woff[warp].y + (ty - sy);
    float bz = woff[warp].z + (tz - sz);

    // arg = a_i + a_j + dot(p_hat_i, p_hat_j), p_hat = SS*p, a = -0.5*|p_hat|^2
    const float S2 = 8.0f * 1.4426950408889634f;   // 8*log2(e)
    const float SS = sqrtf(S2);                    // ~3.397 (scaled step length)

    float4 mylast;
    float mnx = 1e30f, mxx = -1e30f, mny = 1e30f, mxy = -1e30f;
    float mnz = 1e30f, mxz = -1e30f;
    #pragma unroll
    for (int m = 0; m < 8; m++) {
        float x = bx + px[m];
        float y = by + py[m];
        float z = bz + pz[m];
        float xh = SS * x, yh = SS * y, zh = SS * z;
        float a = -0.5f * (xh * xh + yh * yh + zh * zh);
        mylast = make_float4(xh, yh, zh, a);
        g_pts[chain][t * 8 + m + 1] = mylast;
        mnx = fminf(mnx, xh); mxx = fmaxf(mxx, xh);
        mny = fminf(mny, yh); mxy = fmaxf(mxy, yh);
        mnz = fminf(mnz, zh); mxz = fmaxf(mxz, zh);
    }
    if (t == 0) g_pts[chain][0] = make_float4(0.f, 0.f, 0.f, 0.f);
    if (t == 1023) lastpt = mylast;    // point index 8192 = last real point

    // per-chunk bounds: 16-thread segments hold points [128c+1, 128c+129);
    // radius inflated by SS (one step) to cover boundary point 128c.
    #pragma unroll
    for (int d = 8; d > 0; d >>= 1) {
        mnx = fminf(mnx, __shfl_xor_sync(0xffffffffu, mnx, d, 16));
        mxx = fmaxf(mxx, __shfl_xor_sync(0xffffffffu, mxx, d, 16));
        mny = fminf(mny, __shfl_xor_sync(0xffffffffu, mny, d, 16));
        mxy = fmaxf(mxy, __shfl_xor_sync(0xffffffffu, mxy, d, 16));
        mnz = fminf(mnz, __shfl_xor_sync(0xffffffffu, mnz, d, 16));
        mxz = fmaxf(mxz, __shfl_xor_sync(0xffffffffu, mxz, d, 16));
    }
    if ((t & 15) == 0) {
        float hx = 0.5f * (mxx - mnx), hy = 0.5f * (mxy - mny), hz = 0.5f * (mxz - mnz);
        float r = sqrtf(hx * hx + hy * hy + hz * hz) + SS + 1e-2f;
        g_cb[chain * NCHUNK + (t >> 4)] = make_float4(
            0.5f * (mnx + mxx), 0.5f * (mny + mxy), 0.5f * (mnz + mxz), r);
    }
    __syncthreads();

    // padding points at last real point (a=-1e30 -> contribute exactly 0)
    if (t < PADN - NPTS)
        g_pts[chain][NPTS + t] =
            make_float4(lastpt.x, lastpt.y, lastpt.z, -1e30f);

    // chunk 64 contains real point 8192 (= lastpt) + pads at lastpt
    if (t == 0)
        g_cb[chain * NCHUNK + 64] = make_float4(lastpt.x, lastpt.y, lastpt.z, 0.1f);
    // chunks 65..67 are pure pads: far-away center -> every pair culls
    if (t >= 1 && t <= 3)
        g_cb[chain * NCHUNK + 64 + t] = make_float4(2e15f, 2e15f, 2e15f, 0.f);
}

// ---------------------------------------------------------------------------
// Pair kernel: one block per chunk pair (cj >= ci), bounding-sphere cull.
// 512 threads: i = tid & 127, j-segment = tid >> 7 (32 j's per thread).
// jseg is warp-uniform -> smem reads are broadcasts. 4 accumulators break
// the FADD dependence chain. Fixed-point atomic accumulation; last block
// finalizes output and resets state for the next graph replay.
// ---------------------------------------------------------------------------
__global__ void __launch_bounds__(PBLOCK) pair_kernel(float* __restrict__ out) {
    const int p = blockIdx.x;
    const int chain = blockIdx.y;
    const int tid = threadIdx.x;

    // map linear pair index -> (ci, cj)
    int ci = 0, rem = p;
    while (rem >= NCHUNK - ci) { rem -= NCHUNK - ci; ci++; }
    const int cj = ci + rem;

    // bounding-sphere cull
    float4 bi = g_cb[chain * NCHUNK + ci];
    float4 bj = g_cb[chain * NCHUNK + cj];
    float dcx = bi.x - bj.x, dcy = bi.y - bj.y, dcz = bi.z - bj.z;
    float rr = bi.w + bj.w + DCUT_HAT;
    const bool live = (dcx * dcx + dcy * dcy + dcz * dcz <= rr * rr);

    float tot = 0.f;
    if (live) {
        const int il = tid & 127;          // i within chunk
        const int jseg = tid >> 7;         // 0..3, warp-uniform
        const float4* __restrict__ pts = g_pts[chain];
        float4 ipt = pts[ci * CHUNK + il];

        __shared__ float4 tj_sm[CHUNK];
        if (tid < CHUNK) tj_sm[tid] = pts[cj * CHUNK + tid];
        __syncthreads();

        const int jb = jseg * JSEG;
        float a0 = 0.f, a1 = 0.f, a2 = 0.f, a3 = 0.f;

        if (ci != cj) {
            #pragma unroll
            for (int k = 0; k < JSEG; k += 4) {
                #pragma unroll
                for (int u = 0; u < 4; u++) {
                    float4 q = tj_sm[jb + k + u];
                    float m = fmaf(ipt.x, q.x, q.w);
                    m = fmaf(ipt.y, q.y, m);
                    m = fmaf(ipt.z, q.z, m);
                    float arg = fminf(m + ipt.w, 0.0f);
                    float e;
                    asm("ex2.approx.f32 %0, %1;" : "=f"(e) : "f"(arg));
                    if (u == 0) a0 += e; else if (u == 1) a1 += e;
                    else if (u == 2) a2 += e; else a3 += e;
                }
            }
        } else {
            #pragma unroll
            for (int k = 0; k < JSEG; k += 4) {
                #pragma unroll
                for (int u = 0; u < 4; u++) {
                    int j = jb + k + u;
                    float4 q = tj_sm[j];
                    float m = fmaf(ipt.x, q.x, q.w);
                    m = fmaf(ipt.y, q.y, m);
                    m = fmaf(ipt.z, q.z, m);
                    float arg = fminf(m + ipt.w, 0.0f);
                    float e;
                    asm("ex2.approx.f32 %0, %1;" : "=f"(e) : "f"(arg));
                    e = (j > il) ? e : 0.0f;
                    if (u == 0) a0 += e; else if (u == 1) a1 += e;
                    else if (u == 2) a2 += e; else a3 += e;
                }
            }
        }

        float acc = (a0 + a1) + (a2 + a3);

        // block reduction (16 warps)
        #pragma unroll
        for (int d = 16; d > 0; d >>= 1)
            acc += __shfl_down_sync(0xffffffffu, acc, d);
        __shared__ float red[PBLOCK / 32];
        if ((tid & 31) == 0) red[tid >> 5] = acc;
        __syncthreads();
        if (tid == 0) {
            float s = 0.f;
            #pragma unroll
            for (int w = 0; w < PBLOCK / 32; w++) s += red[w];
            tot = s;
        }
    }

    if (tid == 0) {
        if (live && tot > 0.f) {
            unsigned long long q = (unsigned long long)__float2ll_rn(tot * FXSCALE);
            atomicAdd(&g_acc, q);
        }
        __threadfence();
        unsigned int done = atomicAdd(&g_count, 1u);
        if (done == NBLOCKS - 1) {
            unsigned long long raw = atomicAdd(&g_acc, 0ULL);
            double sum = (double)(long long)raw * (1.0 / (double)FXSCALE);
            out[0] = (float)(10.0 * (2.0 * sum + (double)(NCHAIN * NPTS)));
            // reset for next graph replay
            atomicExch(&g_acc, 0ULL);
            atomicExch(&g_count, 0u);
        }
    }
}

extern "C" void kernel_launch(void* const* d_in, const int* in_sizes, int n_in,
                              void* d_out, int out_size) {
    const float* conf = (const float*)d_in[0];
    float* out = (float*)d_out;

    setup_kernel<<<NCHAIN, 1024>>>(conf);
    pair_kernel<<<dim3(NPAIR, NCHAIN), PBLOCK>>>(out);
}

// round 7
// speedup vs baseline: 1.2558x; 1.2558x over previous
#include <cuda_runtime.h>

// Problem constants
#define NSTEPS   8192
#define NPTS     8193            // positions per chain (incl. leading zero row)
#define NCHAIN   2
#define CONFLEN  16388

// Chunking
#define CHUNK    128
#define NCHUNK   68                              // PADN / CHUNK
#define PADN     (NCHUNK * CHUNK)                // 8704
#define NPAIR    (NCHUNK * (NCHUNK + 1) / 2)     // 2346 chunk pairs (cj >= ci)
#define MAXITEMS (NPAIR * NCHAIN)

#define PBLOCK   512                             // 4 j-segments x 128 i
#define JSEG     32                              // j's per thread
#define PGRID    296                             // persistent blocks (2/SM)

// Scaled-space cutoff: dropped pair value <= 2^(-0.5*64) = 2.3e-10
#define DCUT_HAT 8.0f

// Fixed-point scale for deterministic integer accumulation
#define FXSCALE  16777216.0f     // 2^24

// Scratch (no allocations allowed; zero-initialized)
__device__ float4 g_pts[NCHAIN][PADN];           // (x_hat, y_hat, z_hat, a)
__device__ int    g_live[MAXITEMS];              // packed live items
__device__ unsigned int g_live_cnt;              // live item count
__device__ unsigned long long g_acc;             // fixed-point sum
__device__ unsigned int g_count;                 // finished-block counter

// ---------------------------------------------------------------------------
// Setup + plan: positions (prefix sum of unit steps), pre-scale, pads,
// chunk bounds (smem), then cull all chunk pairs and emit a compact live list.
// One block (1024 threads) per chain; each thread handles 8 consecutive steps.
// ---------------------------------------------------------------------------
__global__ void setup_kernel(const float* __restrict__ conf) {
    const int chain = blockIdx.x;
    const float* cf = conf + chain * CONFLEN;
    const int t = threadIdx.x;                 // 0..1023
    const int lane = t & 31, warp = t >> 5;

    const float TWO_PI = 6.2831853071795864769f;

    // local steps + inclusive local prefix
    float px[8], py[8], pz[8];
    float sx = 0.f, sy = 0.f, sz = 0.f;
    const float2* cp = (const float2*)(cf + 4);  // (r1, r2) pairs
    #pragma unroll
    for (int m = 0; m < 8; m++) {
        int k = t * 8 + m;
        float2 rr = cp[k];
        float r1 = rr.x + 0.5f;
        float r2 = rr.y + 0.5f;
        float z  = 1.0f - 2.0f * r2;                    // cos(theta)
        float sth = sqrtf(fmaxf(1.0f - z * z, 0.0f));   // sin(theta)
        float s, c;
        __sincosf(r1 * TWO_PI, &s, &c);
        sx += sth * c;
        sy += sth * s;
        sz += z;
        px[m] = sx; py[m] = sy; pz[m] = sz;
    }

    // warp inclusive scan of thread totals
    float tx = sx, ty = sy, tz = sz;
    #pragma unroll
    for (int d = 1; d < 32; d <<= 1) {
        float ox = __shfl_up_sync(0xffffffffu, tx, d);
        float oy = __shfl_up_sync(0xffffffffu, ty, d);
        float oz = __shfl_up_sync(0xffffffffu, tz, d);
        if (lane >= d) { tx += ox; ty += oy; tz += oz; }
    }

    __shared__ float3 wtot[32];
    __shared__ float3 woff[32];
    __shared__ float4 lastpt;
    __shared__ float4 cb[NCHUNK];               // chunk bounds (cx,cy,cz,r)
    if (lane == 31) wtot[warp] = make_float3(tx, ty, tz);
    __syncthreads();
    if (t == 0) {
        float ax = 0.f, ay = 0.f, az = 0.f;
        #pragma unroll
        for (int w = 0; w < 32; w++) {
            float3 v = wtot[w];
            woff[w] = make_float3(ax, ay, az);
            ax += v.x; ay += v.y; az += v.z;
        }
    }
    __syncthreads();

    // exclusive base for this thread
    float bx = woff[warp].x + (tx - sx);
    float by = woff[warp].y + (ty - sy);
    float bz = woff[warp].z + (tz - sz);

    // arg = a_i + a_j + dot(p_hat_i, p_hat_j), p_hat = SS*p, a = -0.5*|p_hat|^2
    const float S2 = 8.0f * 1.4426950408889634f;   // 8*log2(e)
    const float SS = sqrtf(S2);                    // ~3.397 (scaled step length)

    float4 mylast;
    float mnx = 1e30f, mxx = -1e30f, mny = 1e30f, mxy = -1e30f;
    float mnz = 1e30f, mxz = -1e30f;
    #pragma unroll
    for (int m = 0; m < 8; m++) {
        float x = bx + px[m];
        float y = by + py[m];
        float z = bz + pz[m];
        float xh = SS * x, yh = SS * y, zh = SS * z;
        float a = -0.5f * (xh * xh + yh * yh + zh * zh);
        mylast = make_float4(xh, yh, zh, a);
        g_pts[chain][t * 8 + m + 1] = mylast;
        mnx = fminf(mnx, xh); mxx = fmaxf(mxx, xh);
        mny = fminf(mny, yh); mxy = fmaxf(mxy, yh);
        mnz = fminf(mnz, zh); mxz = fmaxf(mxz, zh);
    }
    if (t == 0) g_pts[chain][0] = make_float4(0.f, 0.f, 0.f, 0.f);
    if (t == 1023) lastpt = mylast;    // point index 8192 = last real point

    // per-chunk bounds: 16-thread segments hold points [128c+1, 128c+129);
    // radius inflated by SS (one step) to cover boundary point 128c.
    #pragma unroll
    for (int d = 8; d > 0; d >>= 1) {
        mnx = fminf(mnx, __shfl_xor_sync(0xffffffffu, mnx, d, 16));
        mxx = fmaxf(mxx, __shfl_xor_sync(0xffffffffu, mxx, d, 16));
        mny = fminf(mny, __shfl_xor_sync(0xffffffffu, mny, d, 16));
        mxy = fmaxf(mxy, __shfl_xor_sync(0xffffffffu, mxy, d, 16));
        mnz = fminf(mnz, __shfl_xor_sync(0xffffffffu, mnz, d, 16));
        mxz = fmaxf(mxz, __shfl_xor_sync(0xffffffffu, mxz, d, 16));
    }
    if ((t & 15) == 0) {
        float hx = 0.5f * (mxx - mnx), hy = 0.5f * (mxy - mny), hz = 0.5f * (mxz - mnz);
        float r = sqrtf(hx * hx + hy * hy + hz * hz) + SS + 1e-2f;
        cb[t >> 4] = make_float4(
            0.5f * (mnx + mxx), 0.5f * (mny + mxy), 0.5f * (mnz + mxz), r);
    }
    __syncthreads();

    // padding points at last real point (a=-1e30 -> contribute exactly 0)
    if (t < PADN - NPTS)
        g_pts[chain][NPTS + t] =
            make_float4(lastpt.x, lastpt.y, lastpt.z, -1e30f);

    // chunk 64 contains real point 8192 (= lastpt) + pads at lastpt
    if (t == 0)
        cb[64] = make_float4(lastpt.x, lastpt.y, lastpt.z, 0.1f);
    // chunks 65..67 are pure pads: far-away center -> every pair culls
    if (t >= 1 && t <= 3)
        cb[64 + t] = make_float4(2e15f, 2e15f, 2e15f, 0.f);
    __syncthreads();

    // ---- plan: cull all chunk pairs for this chain, emit compact list ----
    for (int p = t; p < NPAIR; p += 1024) {
        int ci = 0, rem = p;
        while (rem >= NCHUNK - ci) { rem -= NCHUNK - ci; ci++; }
        int cj = ci + rem;
        float4 bi = cb[ci];
        float4 bj = cb[cj];
        float dcx = bi.x - bj.x, dcy = bi.y - bj.y, dcz = bi.z - bj.z;
        float rr = bi.w + bj.w + DCUT_HAT;
        if (dcx * dcx + dcy * dcy + dcz * dcz <= rr * rr) {
            unsigned int idx = atomicAdd(&g_live_cnt, 1u);
            g_live[idx] = (chain << 16) | (ci << 8) | cj;
        }
    }
}

// ---------------------------------------------------------------------------
// Pair kernel: persistent grid, grid-stride over compact live-item list.
// 512 threads: i = tid & 127, j-segment = tid >> 7 (32 j's per thread).
// jseg is warp-uniform -> smem reads are broadcasts. Per-item fixed-point
// quantization keeps the total independent of list order. Last block
// finalizes output and resets state for the next graph replay.
// ---------------------------------------------------------------------------
__global__ void __launch_bounds__(PBLOCK) pair_kernel(float* __restrict__ out) {
    const int tid = threadIdx.x;
    const int il = tid & 127;          // i within chunk
    const int jb = (tid >> 7) * JSEG;  // j-segment base, warp-uniform

    __shared__ float4 tj_sm[CHUNK];
    __shared__ float red[PBLOCK / 32];

    const unsigned int nitems = g_live_cnt;
    unsigned long long llacc = 0ULL;

    for (unsigned int it = blockIdx.x; it < nitems; it += PGRID) {
        const int item = g_live[it];
        const int chain = item >> 16;
        const int ci = (item >> 8) & 255;
        const int cj = item & 255;

        const float4* __restrict__ pts = g_pts[chain];
        float4 ipt = pts[ci * CHUNK + il];
        if (tid < CHUNK) tj_sm[tid] = pts[cj * CHUNK + tid];
        __syncthreads();

        float a0 = 0.f, a1 = 0.f, a2 = 0.f, a3 = 0.f;
        if (ci != cj) {
            #pragma unroll
            for (int k = 0; k < JSEG; k += 4) {
                #pragma unroll
                for (int u = 0; u < 4; u++) {
                    float4 q = tj_sm[jb + k + u];
                    float m = fmaf(ipt.x, q.x, q.w);
                    m = fmaf(ipt.y, q.y, m);
                    m = fmaf(ipt.z, q.z, m);
                    float arg = fminf(m + ipt.w, 0.0f);
                    float e;
                    asm("ex2.approx.f32 %0, %1;" : "=f"(e) : "f"(arg));
                    if (u == 0) a0 += e; else if (u == 1) a1 += e;
                    else if (u == 2) a2 += e; else a3 += e;
                }
            }
        } else {
            #pragma unroll
            for (int k = 0; k < JSEG; k += 4) {
                #pragma unroll
                for (int u = 0; u < 4; u++) {
                    int j = jb + k + u;
                    float4 q = tj_sm[j];
                    float m = fmaf(ipt.x, q.x, q.w);
                    m = fmaf(ipt.y, q.y, m);
                    m = fmaf(ipt.z, q.z, m);
                    float arg = fminf(m + ipt.w, 0.0f);
                    float e;
                    asm("ex2.approx.f32 %0, %1;" : "=f"(e) : "f"(arg));
                    e = (j > il) ? e : 0.0f;
                    if (u == 0) a0 += e; else if (u == 1) a1 += e;
                    else if (u == 2) a2 += e; else a3 += e;
                }
            }
        }

        float acc = (a0 + a1) + (a2 + a3);
        #pragma unroll
        for (int d = 16; d > 0; d >>= 1)
            acc += __shfl_down_sync(0xffffffffu, acc, d);
        if ((tid & 31) == 0) red[tid >> 5] = acc;
        __syncthreads();
        if (tid == 0) {
            float s = 0.f;
            #pragma unroll
            for (int w = 0; w < PBLOCK / 32; w++) s += red[w];
            // per-item quantization -> order-independent total
            llacc += (unsigned long long)__float2ll_rn(s * FXSCALE);
        }
        __syncthreads();   // protect red[] and tj_sm for next item
    }

    if (tid == 0) {
        if (llacc) atomicAdd(&g_acc, llacc);
        __threadfence();
        unsigned int done = atomicAdd(&g_count, 1u);
        if (done == PGRID - 1) {
            unsigned long long raw = atomicAdd(&g_acc, 0ULL);
            double sum = (double)(long long)raw * (1.0 / (double)FXSCALE);
            out[0] = (float)(10.0 * (2.0 * sum + (double)(NCHAIN * NPTS)));
            // reset for next graph replay (all blocks have read g_live_cnt)
            atomicExch(&g_acc, 0ULL);
            atomicExch(&g_count, 0u);
            atomicExch(&g_live_cnt, 0u);
        }
    }
}

extern "C" void kernel_launch(void* const* d_in, const int* in_sizes, int n_in,
                              void* d_out, int out_size) {
    const float* conf = (const float*)d_in[0];
    float* out = (float*)d_out;

    setup_kernel<<<NCHAIN, 1024>>>(conf);
    pair_kernel<<<PGRID, PBLOCK>>>(out);
}